// round 1
// baseline (speedup 1.0000x reference)
#include <cuda_runtime.h>
#include <cstdint>

#define LNUM 24
#define BB 32
#define DD 1024
#define ED 2048
#define NN 16
#define RR 64
#define VV 50280

typedef unsigned long long ull;

// -------- persistent scratch (feature-major, batch-minor [feat][32]) --------
__device__ float g_x [DD*BB];          // residual stream x_t[d][b]
__device__ float g_xn[DD*BB];          // rmsnorm output
__device__ float g_xz[2*ED*BB];        // in_proj output: rows 0..2047 = xi, 2048..4095 = z
__device__ float g_xc[ED*BB];          // conv+silu output
__device__ float g_dbc[(RR+2*NN)*BB];  // x_proj output (96 rows)
__device__ float g_g [ED*BB];          // gated y*silu(z)

// -------- f32x2 helpers (packed FFMA, 2x FP32 throughput) --------
__device__ __forceinline__ ull dup2(float w) {
    ull r; asm("mov.b64 %0, {%1, %1};" : "=l"(r) : "f"(w)); return r;
}
__device__ __forceinline__ void fma2(ull &a, ull x, ull y) {
    asm("fma.rn.f32x2 %0, %1, %2, %0;" : "+l"(a) : "l"(x), "l"(y));
}
__device__ __forceinline__ float2 unpack2(ull v) {
    float lo, hi; asm("mov.b64 {%0, %1}, %2;" : "=f"(lo), "=f"(hi) : "l"(v));
    return make_float2(lo, hi);
}

__device__ __forceinline__ float sigmoidf_(float z) { return 1.f / (1.f + expf(-z)); }

// ---------------------------------------------------------------------------
// embed: x_t[d][b] = embedding[token[b]][d]
// ---------------------------------------------------------------------------
__global__ void embed_kernel(const int* __restrict__ token, const float* __restrict__ emb) {
    int idx = blockIdx.x * blockDim.x + threadIdx.x;
    if (idx >= DD*BB) return;
    int b = idx & 31, d = idx >> 5;
    g_x[idx] = emb[(size_t)token[b] * DD + d];
}

// ---------------------------------------------------------------------------
// rmsnorm (block 0) + buffer zeroing (other blocks)
// zero_internal=1: zero g_xz and g_dbc (per-layer). extzero: extra region (logits)
// ---------------------------------------------------------------------------
__global__ void rmsnorm_kernel(const float* __restrict__ w,
                               float* extzero, int extn, int zero_internal) {
    if (blockIdx.x == 0) {
        __shared__ float sp[1024];
        __shared__ float sr[32];
        int tid = threadIdx.x;
        int b = tid & 31, d0 = tid >> 5;
        float s = 0.f;
        #pragma unroll
        for (int i = 0; i < 32; i++) { float v = g_x[(d0 + 32*i)*32 + b]; s += v*v; }
        sp[tid] = s;
        __syncthreads();
        if (tid < 32) {
            float t = 0.f;
            #pragma unroll
            for (int j = 0; j < 32; j++) t += sp[j*32 + tid];
            sr[tid] = rsqrtf(t / (float)DD + 1e-5f);
        }
        __syncthreads();
        float rb = sr[b];
        #pragma unroll
        for (int i = 0; i < 32; i++) {
            int d = d0 + 32*i;
            g_xn[d*32 + b] = g_x[d*32 + b] * rb * w[d];
        }
    } else {
        int nb = gridDim.x - 1;
        int base = (blockIdx.x - 1) * 1024 + threadIdx.x;
        int stride = nb * 1024;
        if (zero_internal) {
            for (int i = base; i < 2*ED*BB; i += stride) g_xz[i] = 0.f;
            for (int i = base; i < (RR+2*NN)*BB; i += stride) g_dbc[i] = 0.f;
        }
        if (extzero) {
            for (int i = base; i < extn; i += stride) extzero[i] = 0.f;
        }
    }
}

// ---------------------------------------------------------------------------
// split-K GEMM: C[M][32] += W[M][Kdim] * X[Kdim][32]  (atomicAdd partials)
// block: 128 rows x 32 b; 128 threads; thread tile 8r x 4b using f32x2.
// mode 0: X=g_xn, OUT=g_xz (in_proj)
// mode 1: X=g_g,  OUT=g_x  (out_proj, in-place residual)
// mode 2: X=g_xn, OUT=extOut with index b*VV + r (logits)
// ---------------------------------------------------------------------------
__global__ __launch_bounds__(128)
void gemm_kernel(const float* __restrict__ W, float* extOut,
                 int M, int Kdim, int kslice, int mode) {
    __shared__ float xs[32][34];
    const float* X = (mode == 1) ? g_g : g_xn;
    float* OUT = (mode == 0) ? g_xz : ((mode == 1) ? g_x : extOut);

    int tid = threadIdx.x;
    int bq = tid & 7, rg = tid >> 3;
    int b0 = bq * 4;
    int rbase = blockIdx.x * 128 + rg * 8;
    int k0 = blockIdx.y * kslice;
    int lb = tid & 31, ldd = tid >> 5;

    ull acc[8][2];
    #pragma unroll
    for (int i = 0; i < 8; i++) { acc[i][0] = 0ULL; acc[i][1] = 0ULL; }

    for (int kc = k0; kc < k0 + kslice; kc += 32) {
        #pragma unroll
        for (int i = 0; i < 8; i++)
            xs[ldd + 4*i][lb] = X[(kc + ldd + 4*i)*32 + lb];
        __syncthreads();
        #pragma unroll
        for (int dd = 0; dd < 32; dd += 4) {
            float4 wv[8];
            #pragma unroll
            for (int i = 0; i < 8; i++) {
                int r = rbase + i; if (r >= M) r = M - 1;   // clamp; store guarded
                wv[i] = *(const float4*)(W + (size_t)r * Kdim + kc + dd);
            }
            ull xp0[4], xp1[4];
            #pragma unroll
            for (int t = 0; t < 4; t++) {
                xp0[t] = *(const ull*)&xs[dd + t][b0];
                xp1[t] = *(const ull*)&xs[dd + t][b0 + 2];
            }
            #pragma unroll
            for (int i = 0; i < 8; i++) {
                ull w0 = dup2(wv[i].x), w1 = dup2(wv[i].y),
                    w2 = dup2(wv[i].z), w3 = dup2(wv[i].w);
                fma2(acc[i][0], w0, xp0[0]); fma2(acc[i][1], w0, xp1[0]);
                fma2(acc[i][0], w1, xp0[1]); fma2(acc[i][1], w1, xp1[1]);
                fma2(acc[i][0], w2, xp0[2]); fma2(acc[i][1], w2, xp1[2]);
                fma2(acc[i][0], w3, xp0[3]); fma2(acc[i][1], w3, xp1[3]);
            }
        }
        __syncthreads();
    }

    #pragma unroll
    for (int i = 0; i < 8; i++) {
        int r = rbase + i;
        if (r < M) {
            float2 v01 = unpack2(acc[i][0]);
            float2 v23 = unpack2(acc[i][1]);
            if (mode != 2) {
                atomicAdd(&OUT[r*32 + b0 + 0], v01.x);
                atomicAdd(&OUT[r*32 + b0 + 1], v01.y);
                atomicAdd(&OUT[r*32 + b0 + 2], v23.x);
                atomicAdd(&OUT[r*32 + b0 + 3], v23.y);
            } else {
                atomicAdd(&OUT[(size_t)(b0 + 0)*VV + r], v01.x);
                atomicAdd(&OUT[(size_t)(b0 + 1)*VV + r], v01.y);
                atomicAdd(&OUT[(size_t)(b0 + 2)*VV + r], v23.x);
                atomicAdd(&OUT[(size_t)(b0 + 3)*VV + r], v23.y);
            }
        }
    }
}

// ---------------------------------------------------------------------------
// conv (depthwise K=4) + silu + ci_new output + x_proj split-K partial
// grid: ED/16 = 128 blocks (each owns a 16-wide e-slice), 256 threads
// ---------------------------------------------------------------------------
__global__ void convx_kernel(const float* __restrict__ cw, const float* __restrict__ cb,
                             const float* __restrict__ ci_in, float* __restrict__ ci_out,
                             const float* __restrict__ xw) {
    const int ES = 16;
    __shared__ float xc_s[ES][32];
    __shared__ float ws[ES * 97];
    int tid = threadIdx.x;
    int e0 = blockIdx.x * ES;

    // phase 1: conv+silu for this e-slice
    #pragma unroll
    for (int it = 0; it < 2; it++) {
        int idx = tid + it * 256;       // 0..511
        int el = idx >> 5, b = idx & 31;
        int e = e0 + el;
        float xi = g_xz[e*32 + b];
        const float* cip = ci_in + ((size_t)b * ED + e) * 3;
        float c0 = cip[0], c1 = cip[1], c2 = cip[2];
        float pre = c0*cw[e*4+0] + c1*cw[e*4+1] + c2*cw[e*4+2] + xi*cw[e*4+3] + cb[e];
        float xc = pre * sigmoidf_(pre);
        xc_s[el][b] = xc;
        g_xc[e*32 + b] = xc;
        float* cop = ci_out + ((size_t)b * ED + e) * 3;
        cop[0] = c1; cop[1] = c2; cop[2] = xi;
    }
    // stage x_proj weight slice (96 rows x 16 e)
    for (int i = tid; i < 96 * ES; i += 256) {
        int r = i / ES, el = i % ES;
        ws[el*97 + r] = xw[r*ED + e0 + el];
    }
    __syncthreads();

    // phase 2: partial x_proj over this e-slice
    int b = tid & 31, rg = tid >> 5;     // rg in [0,8)
    float acc[12];
    #pragma unroll
    for (int j = 0; j < 12; j++) acc[j] = 0.f;
    #pragma unroll
    for (int k = 0; k < ES; k++) {
        float xv = xc_s[k][b];
        #pragma unroll
        for (int j = 0; j < 12; j++)
            acc[j] += ws[k*97 + rg + 8*j] * xv;
    }
    #pragma unroll
    for (int j = 0; j < 12; j++)
        atomicAdd(&g_dbc[(rg + 8*j)*32 + b], acc[j]);
}

// ---------------------------------------------------------------------------
// dt_proj + softplus + SSM state update + y + gating
// one thread per (b,e); grid 256 blocks x 256 threads
// ---------------------------------------------------------------------------
__global__ void ssm_kernel(const float* __restrict__ dtw, const float* __restrict__ dtb,
                           const float* __restrict__ alog, const float* __restrict__ Dp,
                           const float* __restrict__ h_in, float* __restrict__ h_out) {
    int idx = blockIdx.x * 256 + threadIdx.x;
    int b = idx & 31, e = idx >> 5;

    // delta = softplus(dbc[0:64] . dtw[e] + dtb[e])
    float acc = dtb[e];
    const float4* dwp = (const float4*)(dtw + (size_t)e * RR);
    #pragma unroll
    for (int k = 0; k < 16; k++) {
        float4 w4 = dwp[k];
        acc += w4.x * g_dbc[(4*k+0)*32 + b];
        acc += w4.y * g_dbc[(4*k+1)*32 + b];
        acc += w4.z * g_dbc[(4*k+2)*32 + b];
        acc += w4.w * g_dbc[(4*k+3)*32 + b];
    }
    float delta = (acc > 20.f) ? acc : log1pf(expf(acc));
    float xc = g_xc[e*32 + b];

    const float* hp = h_in  + ((size_t)b * ED + e) * NN;
    float*       ho = h_out + ((size_t)b * ED + e) * NN;
    const float* ap = alog + (size_t)e * NN;

    float y = 0.f;
    #pragma unroll
    for (int n = 0; n < NN; n++) {
        float A  = -expf(ap[n]);
        float dA = expf(delta * A);
        float Bm = g_dbc[(RR + n)*32 + b];
        float Cm = g_dbc[(RR + NN + n)*32 + b];
        float hn = dA * hp[n] + delta * Bm * xc;
        ho[n] = hn;
        y += hn * Cm;
    }
    y += Dp[e] * xc;
    float z = g_xz[(ED + e)*32 + b];
    g_g[e*32 + b] = y * (z * sigmoidf_(z));
}

// ---------------------------------------------------------------------------
extern "C" void kernel_launch(void* const* d_in, const int* in_sizes, int n_in,
                              void* d_out, int out_size) {
    const int*   token  = (const int*)  d_in[0];
    const float* hs     = (const float*)d_in[1];
    const float* ci     = (const float*)d_in[2];
    const float* emb    = (const float*)d_in[3];
    const float* norm_w = (const float*)d_in[4];
    const float* ipw    = (const float*)d_in[5];
    const float* cw     = (const float*)d_in[6];
    const float* cb     = (const float*)d_in[7];
    const float* xpw    = (const float*)d_in[8];
    const float* dtw    = (const float*)d_in[9];
    const float* dtb    = (const float*)d_in[10];
    const float* alog   = (const float*)d_in[11];
    const float* Dp     = (const float*)d_in[12];
    const float* opw    = (const float*)d_in[13];
    const float* nfw    = (const float*)d_in[14];

    float* out    = (float*)d_out;
    float* logits = out;                                   // [B][V]
    float* hs_out = out + (size_t)BB * VV;                 // [L][B][ED][N]
    float* ci_out = hs_out + (size_t)LNUM * BB * ED * NN;  // [L][B][ED][3]

    embed_kernel<<<(DD*BB + 255)/256, 256>>>(token, emb);

    for (int l = 0; l < LNUM; l++) {
        // rmsnorm + zero xz/dbc
        rmsnorm_kernel<<<9, 1024>>>(norm_w + (size_t)l*DD, nullptr, 0, 1);
        // in_proj: 4096x1024, split-K 8
        gemm_kernel<<<dim3(4096/128, 8), 128>>>(
            ipw + (size_t)l * 2*ED*DD, nullptr, 2*ED, DD, DD/8, 0);
        // conv + x_proj
        convx_kernel<<<ED/16, 256>>>(
            cw + (size_t)l*ED*4, cb + (size_t)l*ED,
            ci + (size_t)l*BB*ED*3, ci_out + (size_t)l*BB*ED*3,
            xpw + (size_t)l*(RR+2*NN)*ED);
        // dt_proj + SSM + gate
        ssm_kernel<<<(ED*BB)/256, 256>>>(
            dtw + (size_t)l*ED*RR, dtb + (size_t)l*ED,
            alog + (size_t)l*ED*NN, Dp + (size_t)l*ED,
            hs + (size_t)l*BB*ED*NN, hs_out + (size_t)l*BB*ED*NN);
        // out_proj + residual (in-place atomic into g_x): 1024x2048, split-K 32
        gemm_kernel<<<dim3(DD/128, 32), 128>>>(
            opw + (size_t)l * DD*ED, nullptr, DD, ED, ED/32, 1);
    }

    // final rmsnorm + zero logits
    rmsnorm_kernel<<<65, 1024>>>(nfw, logits, BB*VV, 0);
    // logits: 50280x1024, split-K 2
    gemm_kernel<<<dim3((VV + 127)/128, 2), 128>>>(emb, logits, VV, DD, DD/2, 2);
}

// round 2
// speedup vs baseline: 1.5445x; 1.5445x over previous
#include <cuda_runtime.h>
#include <cstdint>

#define LNUM 24
#define BB 32
#define DD 1024
#define ED 2048
#define NN 16
#define RR 64
#define VV 50280

typedef unsigned long long ull;

// -------- persistent scratch (feature-major, batch-minor [feat][32]) --------
__device__ float g_x [DD*BB];          // residual stream x_t[d][b]
__device__ float g_xn[DD*BB];          // rmsnorm output
__device__ float g_xz[2*ED*BB];        // in_proj output: rows 0..2047 = xi, 2048..4095 = z
__device__ float g_xc[ED*BB];          // conv+silu output
__device__ float g_dbc[(RR+2*NN)*BB];  // x_proj output (96 rows)
__device__ float g_g [ED*BB];          // gated y*silu(z)

// -------- f32x2 helpers --------
__device__ __forceinline__ ull dup2(float w) {
    ull r; asm("mov.b64 %0, {%1, %1};" : "=l"(r) : "f"(w)); return r;
}
__device__ __forceinline__ void fma2(ull &a, ull x, ull y) {
    asm("fma.rn.f32x2 %0, %1, %2, %0;" : "+l"(a) : "l"(x), "l"(y));
}
__device__ __forceinline__ float2 unpack2(ull v) {
    float lo, hi; asm("mov.b64 {%0, %1}, %2;" : "=f"(lo), "=f"(hi) : "l"(v));
    return make_float2(lo, hi);
}
__device__ __forceinline__ float sigf(float z) { return 1.f / (1.f + __expf(-z)); }

// ---------------------------------------------------------------------------
__global__ void embed_kernel(const int* __restrict__ token, const float* __restrict__ emb) {
    int idx = blockIdx.x * blockDim.x + threadIdx.x;
    if (idx >= DD*BB) return;
    int b = idx & 31, d = idx >> 5;
    g_x[idx] = emb[(size_t)token[b] * DD + d];
}

// ---------------------------------------------------------------------------
// rmsnorm (block 0) + zeroing of accumulation buffers (other blocks)
// ---------------------------------------------------------------------------
__global__ void rmsnorm_kernel(const float* __restrict__ w, int zero_internal) {
    if (blockIdx.x == 0) {
        __shared__ float sp[1024];
        __shared__ float sr[32];
        int tid = threadIdx.x;
        int b = tid & 31, d0 = tid >> 5;
        float s = 0.f;
        #pragma unroll
        for (int i = 0; i < 32; i++) { float v = g_x[(d0 + 32*i)*32 + b]; s += v*v; }
        sp[tid] = s;
        __syncthreads();
        if (tid < 32) {
            float t = 0.f;
            #pragma unroll
            for (int j = 0; j < 32; j++) t += sp[j*32 + tid];
            sr[tid] = rsqrtf(t * (1.f/(float)DD) + 1e-5f);
        }
        __syncthreads();
        float rb = sr[b];
        #pragma unroll
        for (int i = 0; i < 32; i++) {
            int d = d0 + 32*i;
            g_xn[d*32 + b] = g_x[d*32 + b] * rb * w[d];
        }
    } else if (zero_internal) {
        int nb = gridDim.x - 1;
        int base = (blockIdx.x - 1) * 1024 + threadIdx.x;
        int stride = nb * 1024;
        for (int i = base; i < 2*ED*BB/4; i += stride)
            ((float4*)g_xz)[i] = make_float4(0.f,0.f,0.f,0.f);
        for (int i = base; i < (RR+2*NN)*BB; i += stride) g_dbc[i] = 0.f;
    }
}

// ---------------------------------------------------------------------------
// split-K GEMM: C[M][32] (+)= W[M][Kdim] * X[Kdim][32]
// block: 128 rows x 32 b; 128 threads; thread tile 4 rows x 8 batch (f32x2)
// mode 0: X=g_xn, OUT=g_xz (atomic)   mode 1: X=g_g, OUT=g_x (atomic resid)
// mode 2: X=g_xn, OUT=logits [b][VV]  (direct store, no split)
// ---------------------------------------------------------------------------
__global__ __launch_bounds__(128)
void gemm_kernel(const float* __restrict__ W, float* __restrict__ extOut,
                 int M, int Kdim, int kslice, int mode) {
    __shared__ float xs[32][36];
    const float* X = (mode == 1) ? g_g : g_xn;
    float* OUT = (mode == 0) ? g_xz : ((mode == 1) ? g_x : extOut);

    int tid = threadIdx.x;
    int bg = tid & 3;             // 4 b-groups of 8
    int rg = tid >> 2;            // 32 row-groups of 4
    int b0 = bg * 8;
    int rbase = blockIdx.x * 128 + rg * 4;
    int k0 = blockIdx.y * kslice;
    int lb = tid & 31, kd = tid >> 5;

    const float* wp[4];
    #pragma unroll
    for (int i = 0; i < 4; i++) {
        int r = rbase + i; if (r > M-1) r = M-1;   // clamp (stores guarded)
        wp[i] = W + (size_t)r * Kdim + k0;
    }

    ull acc[4][4];
    #pragma unroll
    for (int i = 0; i < 4; i++)
        #pragma unroll
        for (int j = 0; j < 4; j++) acc[i][j] = 0ULL;

    for (int kc = 0; kc < kslice; kc += 32) {
        #pragma unroll
        for (int i = 0; i < 8; i++)
            xs[kd + 4*i][lb] = X[(k0 + kc + kd + 4*i)*32 + lb];
        __syncthreads();
        #pragma unroll
        for (int k4 = 0; k4 < 32; k4 += 4) {
            float4 wv[4];
            #pragma unroll
            for (int i = 0; i < 4; i++)
                wv[i] = *(const float4*)(wp[i] + kc + k4);
            #pragma unroll
            for (int t = 0; t < 4; t++) {
                const ulonglong2* xr = (const ulonglong2*)&xs[k4 + t][b0];
                ulonglong2 p0 = xr[0], p1 = xr[1];
                #pragma unroll
                for (int i = 0; i < 4; i++) {
                    float w = (t == 0) ? wv[i].x : (t == 1) ? wv[i].y
                            : (t == 2) ? wv[i].z : wv[i].w;
                    ull wd = dup2(w);
                    fma2(acc[i][0], wd, p0.x);
                    fma2(acc[i][1], wd, p0.y);
                    fma2(acc[i][2], wd, p1.x);
                    fma2(acc[i][3], wd, p1.y);
                }
            }
        }
        __syncthreads();
    }

    #pragma unroll
    for (int i = 0; i < 4; i++) {
        int r = rbase + i;
        if (r < M) {
            #pragma unroll
            for (int j = 0; j < 4; j++) {
                float2 v = unpack2(acc[i][j]);
                int b = b0 + 2*j;
                if (mode != 2) {
                    atomicAdd(&OUT[r*32 + b    ], v.x);
                    atomicAdd(&OUT[r*32 + b + 1], v.y);
                } else {
                    OUT[(size_t)b*VV + r]       = v.x;
                    OUT[(size_t)(b+1)*VV + r]   = v.y;
                }
            }
        }
    }
}

// ---------------------------------------------------------------------------
// conv (depthwise K=4) + silu + ci_new + x_proj split partial (e-slice of 8)
// grid 256 blocks x 256 threads
// ---------------------------------------------------------------------------
__global__ __launch_bounds__(256)
void convx_kernel(const float* __restrict__ cw, const float* __restrict__ cb,
                  const float* __restrict__ ci_in, float* __restrict__ ci_out,
                  const float* __restrict__ xw) {
    __shared__ float xc_s[8][33];
    __shared__ float ws[8][97];
    int tid = threadIdx.x;
    int e0 = blockIdx.x * 8;

    // phase 1: conv + silu (lanes along e for coalesced ci)
    {
        int el = tid & 7, b = tid >> 3;
        int e = e0 + el;
        float xi = g_xz[e*32 + b];
        const float* cip = ci_in + ((size_t)b * ED + e) * 3;
        float c0 = cip[0], c1 = cip[1], c2 = cip[2];
        float pre = c0*cw[e*4+0] + c1*cw[e*4+1] + c2*cw[e*4+2] + xi*cw[e*4+3] + cb[e];
        float xc = pre * sigf(pre);
        xc_s[el][b] = xc;
        g_xc[e*32 + b] = xc;
        float* cop = ci_out + ((size_t)b * ED + e) * 3;
        cop[0] = c1; cop[1] = c2; cop[2] = xi;
    }
    // stage x_proj weight slice (96 rows x 8 e)
    for (int i = tid; i < 96*8; i += 256) {
        int r = i >> 3, el = i & 7;
        ws[el][r] = xw[(size_t)r * ED + e0 + el];
    }
    __syncthreads();

    // phase 2: partial x_proj over this e-slice
    int b = tid & 31, rg = tid >> 5;     // rg in [0,8)
    float acc[12];
    #pragma unroll
    for (int j = 0; j < 12; j++) acc[j] = 0.f;
    #pragma unroll
    for (int k = 0; k < 8; k++) {
        float xv = xc_s[k][b];
        #pragma unroll
        for (int j = 0; j < 12; j++)
            acc[j] += ws[k][rg + 8*j] * xv;
    }
    #pragma unroll
    for (int j = 0; j < 12; j++)
        atomicAdd(&g_dbc[(rg + 8*j)*32 + b], acc[j]);
}

// ---------------------------------------------------------------------------
// dt_proj + softplus + SSM state update + y + gating
// lanes along e (coalesced h float4 IO); one thread per (b,e)
// ---------------------------------------------------------------------------
__global__ __launch_bounds__(256)
void ssm_kernel(const float* __restrict__ dtw, const float* __restrict__ dtb,
                const float* __restrict__ alog, const float* __restrict__ Dp,
                const float* __restrict__ h_in, float* __restrict__ h_out) {
    int idx = blockIdx.x * 256 + threadIdx.x;
    int e = idx & (ED-1), b = idx >> 11;

    float acc = dtb[e];
    const float4* dwp = (const float4*)(dtw + (size_t)e * RR);
    #pragma unroll
    for (int k = 0; k < 16; k++) {
        float4 w4 = dwp[k];
        acc += w4.x * g_dbc[(4*k+0)*32 + b];
        acc += w4.y * g_dbc[(4*k+1)*32 + b];
        acc += w4.z * g_dbc[(4*k+2)*32 + b];
        acc += w4.w * g_dbc[(4*k+3)*32 + b];
    }
    float delta = (acc > 20.f) ? acc : __logf(1.f + __expf(acc));
    float xc = g_xc[e*32 + b];
    float dxc = delta * xc;

    const float4* hp = (const float4*)(h_in  + ((size_t)b * ED + e) * NN);
    float4*       ho = (float4*)      (h_out + ((size_t)b * ED + e) * NN);
    const float4* ap = (const float4*)(alog + (size_t)e * NN);

    float y = 0.f;
    #pragma unroll
    for (int q = 0; q < 4; q++) {
        float4 h4 = hp[q];
        float4 a4 = ap[q];
        float4 o4;
        {
            float dA = __expf(-dxc > 0.f ? delta * -__expf(a4.x) : delta * -__expf(a4.x)); // keep simple below
            (void)dA;
        }
        float dA0 = __expf(delta * -__expf(a4.x));
        float dA1 = __expf(delta * -__expf(a4.y));
        float dA2 = __expf(delta * -__expf(a4.z));
        float dA3 = __expf(delta * -__expf(a4.w));
        int n0 = 4*q;
        float B0 = g_dbc[(RR + n0 + 0)*32 + b];
        float B1 = g_dbc[(RR + n0 + 1)*32 + b];
        float B2 = g_dbc[(RR + n0 + 2)*32 + b];
        float B3 = g_dbc[(RR + n0 + 3)*32 + b];
        float C0 = g_dbc[(RR + NN + n0 + 0)*32 + b];
        float C1 = g_dbc[(RR + NN + n0 + 1)*32 + b];
        float C2 = g_dbc[(RR + NN + n0 + 2)*32 + b];
        float C3 = g_dbc[(RR + NN + n0 + 3)*32 + b];
        o4.x = dA0 * h4.x + dxc * B0;
        o4.y = dA1 * h4.y + dxc * B1;
        o4.z = dA2 * h4.z + dxc * B2;
        o4.w = dA3 * h4.w + dxc * B3;
        ho[q] = o4;
        y += o4.x * C0 + o4.y * C1 + o4.z * C2 + o4.w * C3;
    }
    y += Dp[e] * xc;
    float z = g_xz[(ED + e)*32 + b];
    g_g[e*32 + b] = y * (z * sigf(z));
}

// ---------------------------------------------------------------------------
extern "C" void kernel_launch(void* const* d_in, const int* in_sizes, int n_in,
                              void* d_out, int out_size) {
    const int*   token  = (const int*)  d_in[0];
    const float* hs     = (const float*)d_in[1];
    const float* ci     = (const float*)d_in[2];
    const float* emb    = (const float*)d_in[3];
    const float* norm_w = (const float*)d_in[4];
    const float* ipw    = (const float*)d_in[5];
    const float* cw     = (const float*)d_in[6];
    const float* cb     = (const float*)d_in[7];
    const float* xpw    = (const float*)d_in[8];
    const float* dtw    = (const float*)d_in[9];
    const float* dtb    = (const float*)d_in[10];
    const float* alog   = (const float*)d_in[11];
    const float* Dp     = (const float*)d_in[12];
    const float* opw    = (const float*)d_in[13];
    const float* nfw    = (const float*)d_in[14];

    float* out    = (float*)d_out;
    float* logits = out;                                   // [B][V]
    float* hs_out = out + (size_t)BB * VV;                 // [L][B][ED][N]
    float* ci_out = hs_out + (size_t)LNUM * BB * ED * NN;  // [L][B][ED][3]

    embed_kernel<<<(DD*BB + 255)/256, 256>>>(token, emb);

    for (int l = 0; l < LNUM; l++) {
        rmsnorm_kernel<<<9, 1024>>>(norm_w + (size_t)l*DD, 1);
        // in_proj: 4096x1024, split-K 8
        gemm_kernel<<<dim3(4096/128, 8), 128>>>(
            ipw + (size_t)l * 2*ED*DD, nullptr, 2*ED, DD, DD/8, 0);
        convx_kernel<<<ED/8, 256>>>(
            cw + (size_t)l*ED*4, cb + (size_t)l*ED,
            ci + (size_t)l*BB*ED*3, ci_out + (size_t)l*BB*ED*3,
            xpw + (size_t)l*(RR+2*NN)*ED);
        ssm_kernel<<<(ED*BB)/256, 256>>>(
            dtw + (size_t)l*ED*RR, dtb + (size_t)l*ED,
            alog + (size_t)l*ED*NN, Dp + (size_t)l*ED,
            hs + (size_t)l*BB*ED*NN, hs_out + (size_t)l*BB*ED*NN);
        // out_proj + residual: 1024x2048, split-K 16
        gemm_kernel<<<dim3(DD/128, 16), 128>>>(
            opw + (size_t)l * DD*ED, nullptr, DD, ED, ED/16, 1);
    }

    // final rmsnorm (no zeroing needed)
    rmsnorm_kernel<<<1, 1024>>>(nfw, 0);
    // logits: 50280x1024, direct store, no split
    gemm_kernel<<<dim3((VV + 127)/128, 1), 128>>>(emb, logits, VV, DD, DD, 2);
}

// round 4
// speedup vs baseline: 1.7254x; 1.1172x over previous
#include <cuda_runtime.h>
#include <cstdint>

#define LNUM 24
#define BB 32
#define DD 1024
#define ED 2048
#define NN 16
#define RR 64
#define VV 50280
#define NBLK 148
#define NTHR 1024
#define NSB (NBLK*8)

typedef unsigned long long ull;

// -------- persistent scratch (feature-major, batch-minor [feat][32]) --------
__device__ float g_x [DD*BB];
__device__ float g_xz[2*ED*BB];
__device__ float g_xc[ED*BB];
__device__ float g_dbc[(RR+2*NN)*BB];
__device__ float g_g [ED*BB];
__device__ float g_ssum[2][BB];
__device__ int   g_count = 0;
__device__ int   g_gen   = 0;

// -------- f32x2 helpers --------
__device__ __forceinline__ ull dup2(float w) {
    ull r; asm("mov.b64 %0, {%1, %1};" : "=l"(r) : "f"(w)); return r;
}
__device__ __forceinline__ void fma2(ull &a, ull x, ull y) {
    asm("fma.rn.f32x2 %0, %1, %2, %0;" : "+l"(a) : "l"(x), "l"(y));
}
__device__ __forceinline__ float2 unpack2(ull v) {
    float lo, hi; asm("mov.b64 {%0, %1}, %2;" : "=f"(lo), "=f"(hi) : "l"(v));
    return make_float2(lo, hi);
}
__device__ __forceinline__ float sigf(float z) { return 1.f / (1.f + __expf(-z)); }

__device__ __forceinline__ void barsub(int sbl) {
    asm volatile("bar.sync %0, %1;" :: "r"(sbl + 1), "r"(128) : "memory");
}

// -------- software grid barrier (replay-safe) --------
__device__ __forceinline__ void gsync() {
    __syncthreads();
    if (threadIdx.x == 0) {
        __threadfence();
        volatile int* vg = &g_gen;
        int gen = *vg;
        if (atomicAdd(&g_count, 1) == NBLK - 1) {
            g_count = 0;
            __threadfence();
            *vg = gen + 1;
        } else {
            while (*vg == gen) { __nanosleep(32); }
        }
        __threadfence();
    }
    __syncthreads();
}

// ---------------------------------------------------------------------------
// subblock GEMM stage: C[M][32] (+)= W[M][Kdim] * X[Kdim][32]
// 1184 subblocks of 128 threads; tile = 64 rows x 32 b x kslice.
// thread tile 2 rows x 8 b (4 f32x2 accs per row).
// MODE 0: X = rmsnorm(g_x) (ssum+nw), OUT = g_xz atomic float4
// MODE 1: X = g_g,                    OUT = g_x  atomic float4 (residual)
// MODE 2: X = rmsnorm(g_x) (nfw),     OUT = logits direct store [b][VV]
// ---------------------------------------------------------------------------
template<int MODE>
__device__ void gemm_stage(const float* __restrict__ W, float* __restrict__ OUT,
                           const float* __restrict__ nw,
                           int M, int Kdim, int kslice, int ksplit, int ntiles,
                           float* __restrict__ sh, const float* __restrict__ ssum) {
    int lt  = threadIdx.x & 127;
    int sbl = threadIdx.x >> 7;
    int sb  = sbl * NBLK + blockIdx.x;
    int bg  = lt & 3, rg = lt >> 2;
    int b0  = bg * 8;
    int lb  = lt & 31, kq = lt >> 5;
    float* xs = sh + sbl * 1088;           // 32 x 34

    float rms = 0.f;
    if (MODE == 0 || MODE == 2)
        rms = rsqrtf(ssum[lb] * (1.f/(float)DD) + 1e-5f);

    for (int t = sb; t < ntiles; t += NSB) {
        int mt = t / ksplit;
        int ks = t - mt * ksplit;
        int rbase = mt * 64 + rg * 2;
        int k0 = ks * kslice;
        int r0c = rbase     < M ? rbase     : M - 1;
        int r1c = rbase + 1 < M ? rbase + 1 : M - 1;
        const float* wp0 = W + (size_t)r0c * Kdim + k0;
        const float* wp1 = W + (size_t)r1c * Kdim + k0;

        ull acc[2][4];
        #pragma unroll
        for (int i = 0; i < 2; i++)
            #pragma unroll
            for (int j = 0; j < 4; j++) acc[i][j] = 0ULL;

        for (int kc = 0; kc < kslice; kc += 32) {
            #pragma unroll
            for (int i = 0; i < 8; i++) {
                int kk = kq + 4*i;
                int kgl = k0 + kc + kk;
                float v;
                if (MODE == 1) v = g_g[kgl*32 + lb];
                else           v = g_x[kgl*32 + lb] * rms * nw[kgl];
                xs[kk*34 + lb] = v;
            }
            barsub(sbl);
            #pragma unroll
            for (int k4 = 0; k4 < 32; k4 += 4) {
                float4 w0 = *(const float4*)(wp0 + kc + k4);
                float4 w1 = *(const float4*)(wp1 + kc + k4);
                #pragma unroll
                for (int tt = 0; tt < 4; tt++) {
                    const ull* xr = (const ull*)&xs[(k4+tt)*34 + b0];
                    ull p0 = xr[0], p1 = xr[1], p2 = xr[2], p3 = xr[3];
                    float f0 = (tt==0)?w0.x:(tt==1)?w0.y:(tt==2)?w0.z:w0.w;
                    float f1 = (tt==0)?w1.x:(tt==1)?w1.y:(tt==2)?w1.z:w1.w;
                    ull wd0 = dup2(f0), wd1 = dup2(f1);
                    fma2(acc[0][0], wd0, p0); fma2(acc[0][1], wd0, p1);
                    fma2(acc[0][2], wd0, p2); fma2(acc[0][3], wd0, p3);
                    fma2(acc[1][0], wd1, p0); fma2(acc[1][1], wd1, p1);
                    fma2(acc[1][2], wd1, p2); fma2(acc[1][3], wd1, p3);
                }
            }
            barsub(sbl);
        }

        #pragma unroll
        for (int i = 0; i < 2; i++) {
            int r = rbase + i;
            if (r < M) {
                float2 a0 = unpack2(acc[i][0]), a1 = unpack2(acc[i][1]);
                float2 a2 = unpack2(acc[i][2]), a3 = unpack2(acc[i][3]);
                if (MODE == 2) {
                    OUT[(size_t)(b0+0)*VV + r] = a0.x;
                    OUT[(size_t)(b0+1)*VV + r] = a0.y;
                    OUT[(size_t)(b0+2)*VV + r] = a1.x;
                    OUT[(size_t)(b0+3)*VV + r] = a1.y;
                    OUT[(size_t)(b0+4)*VV + r] = a2.x;
                    OUT[(size_t)(b0+5)*VV + r] = a2.y;
                    OUT[(size_t)(b0+6)*VV + r] = a3.x;
                    OUT[(size_t)(b0+7)*VV + r] = a3.y;
                } else {
                    atomicAdd((float4*)&OUT[r*32 + b0],
                              make_float4(a0.x, a0.y, a1.x, a1.y));
                    atomicAdd((float4*)&OUT[r*32 + b0 + 4],
                              make_float4(a2.x, a2.y, a3.x, a3.y));
                }
            }
        }
    }
}

// ---------------------------------------------------------------------------
__global__ __launch_bounds__(NTHR, 1)
void mega_kernel(const int* __restrict__ token, const float* __restrict__ hs,
                 const float* __restrict__ ci, const float* __restrict__ emb,
                 const float* __restrict__ norm_w, const float* __restrict__ ipw,
                 const float* __restrict__ cw, const float* __restrict__ cb,
                 const float* __restrict__ xpw, const float* __restrict__ dtw,
                 const float* __restrict__ dtb, const float* __restrict__ alog,
                 const float* __restrict__ Dp, const float* __restrict__ opw,
                 const float* __restrict__ nfw,
                 float* __restrict__ logits, float* __restrict__ hs_out,
                 float* __restrict__ ci_out) {
    __shared__ float sh[8 * 1088];
    const int tid = threadIdx.x, bid = blockIdx.x;

    // ---- S0: embed + zero ssum/xz/dbc ----
    if (bid < 32) {
        int idx = bid * NTHR + tid;         // 32768 items
        int b = idx & 31, d = idx >> 5;
        g_x[idx] = emb[(size_t)token[b] * DD + d];
    } else {
        int z = (bid - 32) * NTHR + tid, zs = 116 * NTHR;
        for (int i = z; i < 2*ED*BB/4; i += zs)
            ((float4*)g_xz)[i] = make_float4(0.f, 0.f, 0.f, 0.f);
        if (z < (RR + 2*NN) * BB) g_dbc[z] = 0.f;
        if (z < 64) ((float*)g_ssum)[z] = 0.f;
    }
    gsync();

    for (int l = 0; l < LNUM; l++) {
        // ---- S1: rms partials (blocks 0..31) + zero xz/dbc/ssum-next ----
        if (l > 0) {
            if (bid < 32) {
                int dd = tid >> 5, b = tid & 31;
                float v = g_x[(bid * 32 + dd) * 32 + b];
                sh[tid] = v * v;
                __syncthreads();
                if (tid < 32) {
                    float s = 0.f;
                    #pragma unroll
                    for (int j = 0; j < 32; j++) s += sh[j*32 + tid];
                    atomicAdd(&g_ssum[l & 1][tid], s);
                }
            } else {
                int z = (bid - 32) * NTHR + tid, zs = 116 * NTHR;
                for (int i = z; i < 2*ED*BB/4; i += zs)
                    ((float4*)g_xz)[i] = make_float4(0.f, 0.f, 0.f, 0.f);
                if (z < (RR + 2*NN) * BB) g_dbc[z] = 0.f;
                if (z < 32) g_ssum[(l + 1) & 1][z] = 0.f;
            }
        } else {
            // layer 0: xz/dbc already zeroed in S0; just rms partials + zero ssum[1]
            if (bid < 32) {
                int dd = tid >> 5, b = tid & 31;
                float v = g_x[(bid * 32 + dd) * 32 + b];
                sh[tid] = v * v;
                __syncthreads();
                if (tid < 32) {
                    float s = 0.f;
                    #pragma unroll
                    for (int j = 0; j < 32; j++) s += sh[j*32 + tid];
                    atomicAdd(&g_ssum[0][tid], s);
                }
            } else {
                int z = (bid - 32) * NTHR + tid;
                if (z < 32) g_ssum[1][z] = 0.f;
            }
        }
        gsync();

        // ---- S2: in_proj 4096x1024, tiles 64x(K/8), ntiles 512 ----
        gemm_stage<0>(ipw + (size_t)l * 2*ED*DD, g_xz, norm_w + (size_t)l * DD,
                      2*ED, DD, 128, 8, 512, sh, g_ssum[l & 1]);
        gsync();

        // ---- S3: conv + silu + ci_out + fused x_proj partials ----
        {
            int lt = tid & 127, sbl = tid >> 7;
            int sb = sbl * NBLK + bid;
            float* xc = sh + sbl * 1088;       // 16 x 33
            const float* cwl = cw + (size_t)l * ED * 4;
            const float* cbl = cb + (size_t)l * ED;
            const float* cil = ci + (size_t)l * BB * ED * 3;
            float* col = ci_out + (size_t)l * BB * ED * 3;
            const float* xwl = xpw + (size_t)l * (RR + 2*NN) * ED;
            if (sb < 128) {                    // 128 slices of 16 e
                int e0 = sb * 16;
                #pragma unroll
                for (int it = 0; it < 4; it++) {
                    int item = lt + 128 * it;
                    int el = item & 15, b = item >> 4;
                    int e = e0 + el;
                    float xi = g_xz[e*32 + b];
                    const float* cip = cil + ((size_t)b * ED + e) * 3;
                    float c0 = cip[0], c1 = cip[1], c2 = cip[2];
                    float4 w4 = *(const float4*)(cwl + e*4);
                    float pre = c0*w4.x + c1*w4.y + c2*w4.z + xi*w4.w + cbl[e];
                    float v = pre * sigf(pre);
                    xc[el*33 + b] = v;
                    g_xc[e*32 + b] = v;
                    float* cop = col + ((size_t)b * ED + e) * 3;
                    cop[0] = c1; cop[1] = c2; cop[2] = xi;
                }
                barsub(sbl);
                int b = lt & 31, rg = lt >> 5;   // rg 0..3
                float acc[24];
                #pragma unroll
                for (int j = 0; j < 24; j++) acc[j] = 0.f;
                #pragma unroll
                for (int k = 0; k < 16; k++) {
                    float xv = xc[k*33 + b];
                    #pragma unroll
                    for (int j = 0; j < 24; j++)
                        acc[j] += xwl[(size_t)(rg + 4*j) * ED + e0 + k] * xv;
                }
                #pragma unroll
                for (int j = 0; j < 24; j++)
                    atomicAdd(&g_dbc[(rg + 4*j)*32 + b], acc[j]);
            }
        }
        gsync();

        // ---- S4: dt_proj + softplus + SSM + gate ----
        {
            int idx = bid * NTHR + tid;
            if (idx < ED * BB) {
                int e = idx & (ED - 1), b = idx >> 11;
                const float* dtwl = dtw + (size_t)l * ED * RR;
                float acc = dtb[(size_t)l * ED + e];
                const float4* dwp = (const float4*)(dtwl + (size_t)e * RR);
                #pragma unroll
                for (int k = 0; k < 16; k++) {
                    float4 w4 = dwp[k];
                    acc += w4.x * g_dbc[(4*k+0)*32 + b];
                    acc += w4.y * g_dbc[(4*k+1)*32 + b];
                    acc += w4.z * g_dbc[(4*k+2)*32 + b];
                    acc += w4.w * g_dbc[(4*k+3)*32 + b];
                }
                float delta = (acc > 20.f) ? acc : __logf(1.f + __expf(acc));
                float xc = g_xc[e*32 + b];
                float dxc = delta * xc;
                const float4* hp = (const float4*)(hs + (size_t)l*BB*ED*NN
                                                      + ((size_t)b*ED + e)*NN);
                float4* ho = (float4*)(hs_out + (size_t)l*BB*ED*NN
                                              + ((size_t)b*ED + e)*NN);
                const float4* ap = (const float4*)(alog + (size_t)l*ED*NN
                                                        + (size_t)e*NN);
                float y = 0.f;
                #pragma unroll
                for (int q = 0; q < 4; q++) {
                    float4 h4 = hp[q], a4 = ap[q], o4;
                    float dA0 = __expf(delta * -__expf(a4.x));
                    float dA1 = __expf(delta * -__expf(a4.y));
                    float dA2 = __expf(delta * -__expf(a4.z));
                    float dA3 = __expf(delta * -__expf(a4.w));
                    int n0 = 4*q;
                    o4.x = dA0*h4.x + dxc * g_dbc[(RR+n0+0)*32 + b];
                    o4.y = dA1*h4.y + dxc * g_dbc[(RR+n0+1)*32 + b];
                    o4.z = dA2*h4.z + dxc * g_dbc[(RR+n0+2)*32 + b];
                    o4.w = dA3*h4.w + dxc * g_dbc[(RR+n0+3)*32 + b];
                    ho[q] = o4;
                    y += o4.x * g_dbc[(RR+NN+n0+0)*32 + b];
                    y += o4.y * g_dbc[(RR+NN+n0+1)*32 + b];
                    y += o4.z * g_dbc[(RR+NN+n0+2)*32 + b];
                    y += o4.w * g_dbc[(RR+NN+n0+3)*32 + b];
                }
                y += Dp[(size_t)l * ED + e] * xc;
                float z = g_xz[(ED + e)*32 + b];
                g_g[e*32 + b] = y * (z * sigf(z));
            }
        }
        gsync();

        // ---- S5: out_proj 1024x2048 + residual, tiles 64x(K/32), ntiles 512 ----
        gemm_stage<1>(opw + (size_t)l * DD * ED, g_x, nullptr,
                      DD, ED, 64, 32, 512, sh, nullptr);
        gsync();
    }

    // ---- final rms partials into ssum[0] (zeroed at l=23's S1) ----
    if (bid < 32) {
        int dd = tid >> 5, b = tid & 31;
        float v = g_x[(bid * 32 + dd) * 32 + b];
        sh[tid] = v * v;
        __syncthreads();
        if (tid < 32) {
            float s = 0.f;
            #pragma unroll
            for (int j = 0; j < 32; j++) s += sh[j*32 + tid];
            atomicAdd(&g_ssum[0][tid], s);
        }
    }
    gsync();

    // ---- logits GEMM 50280x1024, full-K tiles, direct store ----
    gemm_stage<2>(emb, logits, nfw, VV, DD, DD, 1, 786, sh, g_ssum[0]);
}

// ---------------------------------------------------------------------------
extern "C" void kernel_launch(void* const* d_in, const int* in_sizes, int n_in,
                              void* d_out, int out_size) {
    const int*   token  = (const int*)  d_in[0];
    const float* hs     = (const float*)d_in[1];
    const float* ci     = (const float*)d_in[2];
    const float* emb    = (const float*)d_in[3];
    const float* norm_w = (const float*)d_in[4];
    const float* ipw    = (const float*)d_in[5];
    const float* cw     = (const float*)d_in[6];
    const float* cb     = (const float*)d_in[7];
    const float* xpw    = (const float*)d_in[8];
    const float* dtw    = (const float*)d_in[9];
    const float* dtb    = (const float*)d_in[10];
    const float* alog   = (const float*)d_in[11];
    const float* Dp     = (const float*)d_in[12];
    const float* opw    = (const float*)d_in[13];
    const float* nfw    = (const float*)d_in[14];

    float* out    = (float*)d_out;
    float* logits = out;
    float* hs_out = out + (size_t)BB * VV;
    float* ci_out = hs_out + (size_t)LNUM * BB * ED * NN;

    mega_kernel<<<NBLK, NTHR>>>(token, hs, ci, emb, norm_w, ipw, cw, cb, xpw,
                                dtw, dtb, alog, Dp, opw, nfw,
                                logits, hs_out, ci_out);
}